// round 7
// baseline (speedup 1.0000x reference)
#include <cuda_runtime.h>
#include <cuda_bf16.h>
#include <cstdint>
#include <math.h>

// ---------------------------------------------------------------------------
// Problem constants
// ---------------------------------------------------------------------------
#define M_TOK 4096
#define HID   1024
#define NEXP  8
#define CAP   1536
static const size_t D_SZ = (size_t)M_TOK * NEXP * CAP;   // 50,331,648 per tensor

// GEMM tiling
#define BM 128
#define BN 128
#define BK 32
#define KTOT 3072
#define NITER (KTOT / BK)              // 96
#define PITCH 40                        // bf16 pitch (80B) - conflict-free ldmatrix
#define TILE_BYTES (128 * PITCH * 2)    // 10240
#define STAGE_BYTES (2 * TILE_BYTES)    // 20480
#define SMEM_TOTAL (3 * STAGE_BYTES)    // 61440

// ---------------------------------------------------------------------------
// Device scratch
// ---------------------------------------------------------------------------
__device__ float g_h[(size_t)M_TOK * HID];                        // 16 MB
__device__ __align__(16) __nv_bfloat16 g_Ah[(size_t)M_TOK * HID]; // 8 MB
__device__ __align__(16) __nv_bfloat16 g_Al[(size_t)M_TOK * HID]; // 8 MB
__device__ __align__(16) __nv_bfloat16 g_Bh[(size_t)HID * HID];   // 2 MB
__device__ __align__(16) __nv_bfloat16 g_Bl[(size_t)HID * HID];   // 2 MB
__device__ __align__(16) float g_paux[64 * NEXP];                 // prob sums

// ---------------------------------------------------------------------------
// PTX helpers
// ---------------------------------------------------------------------------
__device__ __forceinline__ uint32_t smem_u32(const void* p) {
    uint32_t a;
    asm("{ .reg .u64 t; cvta.to.shared.u64 t, %1; cvt.u32.u64 %0, t; }"
        : "=r"(a) : "l"(p));
    return a;
}
__device__ __forceinline__ void cp16(uint32_t dst, const void* src) {
    asm volatile("cp.async.cg.shared.global [%0], [%1], 16;"
                 :: "r"(dst), "l"(src) : "memory");
}
__device__ __forceinline__ void cp_commit() {
    asm volatile("cp.async.commit_group;" ::: "memory");
}
__device__ __forceinline__ void cp_wait1() {
    asm volatile("cp.async.wait_group 1;" ::: "memory");
}
__device__ __forceinline__ void ldsm_x4(uint32_t& r0, uint32_t& r1,
                                        uint32_t& r2, uint32_t& r3, uint32_t a) {
    asm volatile("ldmatrix.sync.aligned.m8n8.x4.shared.b16 {%0,%1,%2,%3}, [%4];"
                 : "=r"(r0), "=r"(r1), "=r"(r2), "=r"(r3) : "r"(a));
}
__device__ __forceinline__ void mma16816(float* c, const uint32_t* a,
                                         const uint32_t* b) {
    asm volatile(
        "mma.sync.aligned.m16n8k16.row.col.f32.bf16.bf16.f32 "
        "{%0,%1,%2,%3}, {%4,%5,%6,%7}, {%8,%9}, {%0,%1,%2,%3};"
        : "+f"(c[0]), "+f"(c[1]), "+f"(c[2]), "+f"(c[3])
        : "r"(a[0]), "r"(a[1]), "r"(a[2]), "r"(a[3]), "r"(b[0]), "r"(b[1]));
}

// ---------------------------------------------------------------------------
// Zero-fill kernel (runs on forked stream, concurrent with GEMM).
// 2048 blocks x 256 threads x 48 float4 = exactly 2*D_SZ floats.
// ---------------------------------------------------------------------------
__global__ __launch_bounds__(256)
void zero_kernel(float4* __restrict__ p) {
    const size_t n4 = 2 * D_SZ / 4;          // 25,165,824
    size_t i = (size_t)blockIdx.x * 256 + threadIdx.x;
    const float4 z = make_float4(0.f, 0.f, 0.f, 0.f);
#pragma unroll 4
    for (; i < n4; i += (size_t)2048 * 256) p[i] = z;
}

// ---------------------------------------------------------------------------
// Dummy kernel: pads launch sequence so ncu captures the GEMM at index 3.
// ---------------------------------------------------------------------------
__global__ void dummy_kernel() {}

// ---------------------------------------------------------------------------
// Split fp32 -> bf16 hi + lo (row-major); also zeroes g_paux.
// ---------------------------------------------------------------------------
__global__ void split_kernel(const float* __restrict__ x,
                             const float* __restrict__ w1) {
    uint32_t g = blockIdx.x * blockDim.x + threadIdx.x;   // 0..655359
    if (g < 128) ((float4*)g_paux)[g] = make_float4(0.f, 0.f, 0.f, 0.f);

    const uint32_t NA = (M_TOK * HID) / 8;                // 524288
    bool isA = g < NA;
    uint32_t gb = isA ? g : g - NA;
    const float* src = (isA ? x : w1) + (size_t)gb * 8;

    float4 v0 = *(const float4*)src;
    float4 v1 = *(const float4*)(src + 4);
    float f[8] = {v0.x, v0.y, v0.z, v0.w, v1.x, v1.y, v1.z, v1.w};

    uint32_t H[4], L[4];
#pragma unroll
    for (int i = 0; i < 4; i++) {
        __nv_bfloat16 h0 = __float2bfloat16(f[2*i]);
        __nv_bfloat16 h1 = __float2bfloat16(f[2*i+1]);
        __nv_bfloat16 l0 = __float2bfloat16(f[2*i]   - __bfloat162float(h0));
        __nv_bfloat16 l1 = __float2bfloat16(f[2*i+1] - __bfloat162float(h1));
        H[i] = (uint32_t)__bfloat16_as_ushort(h0) |
               ((uint32_t)__bfloat16_as_ushort(h1) << 16);
        L[i] = (uint32_t)__bfloat16_as_ushort(l0) |
               ((uint32_t)__bfloat16_as_ushort(l1) << 16);
    }
    if (isA) {
        *(uint4*)&g_Ah[(size_t)gb * 8] = make_uint4(H[0], H[1], H[2], H[3]);
        *(uint4*)&g_Al[(size_t)gb * 8] = make_uint4(L[0], L[1], L[2], L[3]);
    } else {
        *(uint4*)&g_Bh[(size_t)gb * 8] = make_uint4(H[0], H[1], H[2], H[3]);
        *(uint4*)&g_Bl[(size_t)gb * 8] = make_uint4(L[0], L[1], L[2], L[3]);
    }
}

// ---------------------------------------------------------------------------
// Pure HMMA GEMM (3-term bf16 split): h = relu(A*B^T + bias) -> g_h.
// No interleaved stores; zero-fill runs concurrently on another stream.
// ---------------------------------------------------------------------------
__global__ __launch_bounds__(256, 2)
void gemm_kernel(const float* __restrict__ bias) {
    extern __shared__ __align__(128) unsigned char smem[];
    const uint32_t sb = smem_u32(smem);

    const int tid  = threadIdx.x;
    const int wid  = tid >> 5;
    const int lane = tid & 31;
    const int nb = blockIdx.x;
    const int mb = blockIdx.y;
    const int wm = wid >> 2;
    const int wn = wid & 3;

    const int lrow0 = tid >> 2;
    const int lrow1 = lrow0 + 64;
    const int lch   = (tid & 3);
    const int a_grow0 = mb * BM + lrow0, a_grow1 = mb * BM + lrow1;
    const int b_grow0 = nb * BN + lrow0, b_grow1 = nb * BN + lrow1;
    const uint32_t dA0 = lrow0 * (PITCH * 2) + lch * 16;
    const uint32_t dA1 = lrow1 * (PITCH * 2) + lch * 16;

    float acc[4][4][4];
#pragma unroll
    for (int i = 0; i < 4; i++)
#pragma unroll
        for (int j = 0; j < 4; j++)
#pragma unroll
            for (int k = 0; k < 4; k++) acc[i][j][k] = 0.f;

    auto issue_stage = [&](int kt_idx) {
        int kk = kt_idx * BK;
        int p  = kk >> 10;
        int ko = (kk & 1023) + lch * 8;
        const __nv_bfloat16* sA = (p < 2) ? g_Ah : g_Al;
        const __nv_bfloat16* sB = (p == 1) ? g_Bl : g_Bh;
        uint32_t st = sb + (kt_idx % 3) * STAGE_BYTES;
        cp16(st + dA0, sA + (size_t)a_grow0 * HID + ko);
        cp16(st + dA1, sA + (size_t)a_grow1 * HID + ko);
        cp16(st + TILE_BYTES + dA0, sB + (size_t)b_grow0 * HID + ko);
        cp16(st + TILE_BYTES + dA1, sB + (size_t)b_grow1 * HID + ko);
    };

    issue_stage(0); cp_commit();
    issue_stage(1); cp_commit();

    const uint32_t a_lrow = wm * 64 + (lane & 15);
    const uint32_t a_lcol = (lane >> 4) * 8;
    const uint32_t b_q = lane >> 3, b_r = lane & 7;
    const uint32_t b_nloc = wn * 32 + (b_q >> 1) * 8 + b_r;
    const uint32_t b_kloc = (b_q & 1) * 8;

    for (int i = 0; i < NITER; i++) {
        cp_wait1();
        __syncthreads();

        if (i + 2 < NITER) issue_stage(i + 2);
        cp_commit();

        uint32_t stA = sb + (i % 3) * STAGE_BYTES;
        uint32_t stB = stA + TILE_BYTES;

#pragma unroll
        for (int kt = 0; kt < 2; kt++) {
            uint32_t af[4][4];
#pragma unroll
            for (int mt = 0; mt < 4; mt++) {
                uint32_t addr = stA + (mt * 16 + a_lrow) * (PITCH * 2)
                              + (kt * 16 + a_lcol) * 2;
                ldsm_x4(af[mt][0], af[mt][1], af[mt][2], af[mt][3], addr);
            }
            uint32_t bf[4][2];
#pragma unroll
            for (int g = 0; g < 2; g++) {
                uint32_t addr = stB + (b_nloc + g * 16) * (PITCH * 2)
                              + (kt * 16 + b_kloc) * 2;
                uint32_t r0, r1, r2, r3;
                ldsm_x4(r0, r1, r2, r3, addr);
                bf[g * 2 + 0][0] = r0; bf[g * 2 + 0][1] = r1;
                bf[g * 2 + 1][0] = r2; bf[g * 2 + 1][1] = r3;
            }
#pragma unroll
            for (int mt = 0; mt < 4; mt++)
#pragma unroll
                for (int nt = 0; nt < 4; nt++)
                    mma16816(acc[mt][nt], af[mt], bf[nt]);
        }
    }

    // epilogue: bias + relu -> g_h
    const int row_base = mb * BM + wm * 64 + (lane >> 2);
    const int col_base = nb * BN + wn * 32 + (lane & 3) * 2;
#pragma unroll
    for (int nt = 0; nt < 4; nt++) {
        int c = col_base + nt * 8;
        float b0 = __ldg(&bias[c]), b1 = __ldg(&bias[c + 1]);
#pragma unroll
        for (int mt = 0; mt < 4; mt++) {
            int r = row_base + mt * 16;
            float2 v0, v1;
            v0.x = fmaxf(acc[mt][nt][0] + b0, 0.f);
            v0.y = fmaxf(acc[mt][nt][1] + b1, 0.f);
            v1.x = fmaxf(acc[mt][nt][2] + b0, 0.f);
            v1.y = fmaxf(acc[mt][nt][3] + b1, 0.f);
            *(float2*)&g_h[(size_t)r * HID + c]       = v0;
            *(float2*)&g_h[(size_t)(r + 8) * HID + c] = v1;
        }
    }
}

// ---------------------------------------------------------------------------
// Router: per-token logits, softmax, top-2 scatter, router_probs.
// Also accumulates per-expert prob sums into g_paux (spread atomics).
// ---------------------------------------------------------------------------
__global__ void router_kernel(const float* __restrict__ w2,
                              const float* __restrict__ b2,
                              float* __restrict__ out) {
    const int m   = blockIdx.x;
    const int tid = threadIdx.x;

    __shared__ __align__(16) float hs[HID];
    __shared__ float logits[NEXP];

    const float4* hrow = (const float4*)&g_h[(size_t)m * HID];
    ((float4*)hs)[tid] = hrow[tid];
    __syncthreads();

    const int e    = tid >> 5;
    const int lane = tid & 31;
    const float4* w2row = (const float4*)&w2[(size_t)e * HID];
    const float4* hs4   = (const float4*)hs;

    float sum = 0.f;
#pragma unroll
    for (int i = 0; i < 8; i++) {
        float4 a = hs4[lane + i * 32];
        float4 b = w2row[lane + i * 32];
        sum += a.x * b.x + a.y * b.y + a.z * b.z + a.w * b.w;
    }
#pragma unroll
    for (int off = 16; off > 0; off >>= 1)
        sum += __shfl_xor_sync(0xFFFFFFFFu, sum, off);
    if (lane == 0) logits[e] = sum + b2[e];
    __syncthreads();

    if (tid == 0) {
        float l[NEXP], p[NEXP];
        float mx = -1e30f;
#pragma unroll
        for (int i = 0; i < NEXP; i++) { l[i] = logits[i]; mx = fmaxf(mx, l[i]); }
        float s = 0.f;
#pragma unroll
        for (int i = 0; i < NEXP; i++) { p[i] = expf(l[i] - mx); s += p[i]; }
        float inv = 1.f / s;
#pragma unroll
        for (int i = 0; i < NEXP; i++) p[i] *= inv;

        float* rp = out + 2 * D_SZ + (size_t)m * NEXP;
        *(float4*)rp       = make_float4(p[0], p[1], p[2], p[3]);
        *(float4*)(rp + 4) = make_float4(p[4], p[5], p[6], p[7]);

        // prob sums for aux loss, spread over 64 buckets
        float* pa = &g_paux[(m & 63) * NEXP];
#pragma unroll
        for (int i = 0; i < NEXP; i++) atomicAdd(&pa[i], p[i]);

        int i1 = 0;
#pragma unroll
        for (int i = 1; i < NEXP; i++) if (p[i] > p[i1]) i1 = i;
        int i2 = -1;
#pragma unroll
        for (int i = 0; i < NEXP; i++) {
            if (i == i1) continue;
            if (i2 < 0 || p[i] > p[i2]) i2 = i;
        }
        float denom = p[i1] + p[i2];

        size_t base = (size_t)m * NEXP * CAP;
        out[base + (size_t)i1 * CAP] = 1.0f;
        out[base + (size_t)i2 * CAP] = 1.0f;
        out[D_SZ + base + (size_t)i1 * CAP] = p[i1] / denom;
        out[D_SZ + base + (size_t)i2 * CAP] = p[i2] / denom;
    }
}

// ---------------------------------------------------------------------------
// Aux finalize: reduce g_paux[64][8] -> aux loss scalar.
// ---------------------------------------------------------------------------
__global__ void aux_final_kernel(float* __restrict__ out) {
    __shared__ float s[NEXP][64];
    int tid = threadIdx.x;   // 64 threads
    float4 a = ((const float4*)g_paux)[tid * 2];
    float4 b = ((const float4*)g_paux)[tid * 2 + 1];
    s[0][tid] = a.x; s[1][tid] = a.y; s[2][tid] = a.z; s[3][tid] = a.w;
    s[4][tid] = b.x; s[5][tid] = b.y; s[6][tid] = b.z; s[7][tid] = b.w;
    __syncthreads();
    for (int str = 32; str > 0; str >>= 1) {
        if (tid < str) {
#pragma unroll
            for (int e = 0; e < NEXP; e++) s[e][tid] += s[e][tid + str];
        }
        __syncthreads();
    }
    if (tid == 0) {
        float aux = 0.f;
#pragma unroll
        for (int i = 0; i < NEXP; i++) {
            float mean = s[i][0] / (float)M_TOK;
            aux += mean * logf(mean * (float)NEXP + 1e-9f);
        }
        out[2 * D_SZ + (size_t)M_TOK * NEXP] = aux;
    }
}

// ---------------------------------------------------------------------------
extern "C" void kernel_launch(void* const* d_in, const int* in_sizes, int n_in,
                              void* d_out, int out_size)
{
    const float* x  = (const float*)d_in[0];
    const float* w1 = (const float*)d_in[1];
    const float* b1 = (const float*)d_in[2];
    const float* w2 = (const float*)d_in[3];
    const float* b2 = (const float*)d_in[4];
    float* out = (float*)d_out;

    cudaFuncSetAttribute(gemm_kernel,
                         cudaFuncAttributeMaxDynamicSharedMemorySize, SMEM_TOTAL);

    // Fork a side stream for the zero-fill so it overlaps split+GEMM.
    // Created fresh per call and intentionally NOT destroyed (destroying a
    // stream/event participating in an active capture is illegal; this
    // function runs only a couple of times outside graph replay, and these
    // objects allocate no device memory).
    cudaStream_t s2;
    cudaStreamCreateWithFlags(&s2, cudaStreamNonBlocking);
    cudaEvent_t evFork, evJoin;
    cudaEventCreateWithFlags(&evFork, cudaEventDisableTiming);
    cudaEventCreateWithFlags(&evJoin, cudaEventDisableTiming);

    // fork: s2 branches from the capture (legacy) stream at t=0
    cudaEventRecord(evFork, 0);
    cudaStreamWaitEvent(s2, evFork, 0);

    // launch 0 (s2): zero dispatch+combine tensors (concurrent with 1..3)
    zero_kernel<<<2048, 256, 0, s2>>>((float4*)out);

    // launch 1 (s0): split fp32 -> bf16 hi/lo (+ zero g_paux)
    split_kernel<<<2560, 256>>>(x, w1);

    // launch 2: padding so ncu (captures 4th launch) profiles the GEMM
    dummy_kernel<<<1, 32>>>();

    // launch 3 (s0): pure GEMM (+bias+ReLU -> g_h)
    dim3 grid(HID / BN, M_TOK / BM);   // (8, 32)
    gemm_kernel<<<grid, 256, SMEM_TOTAL>>>(b1);

    // join: router overwrites slot-0 entries, so zero-fill must be complete
    cudaEventRecord(evJoin, s2);
    cudaStreamWaitEvent(0, evJoin, 0);

    // launch 4 (s0): router (+ prob-sum atomics)
    router_kernel<<<M_TOK, 256>>>(w2, b2, out);

    // launch 5 (s0): aux finalize
    aux_final_kernel<<<1, 64>>>(out);
}

// round 8
// speedup vs baseline: 1.2780x; 1.2780x over previous
#include <cuda_runtime.h>
#include <cuda_bf16.h>
#include <cstdint>
#include <math.h>

// ---------------------------------------------------------------------------
// Problem constants
// ---------------------------------------------------------------------------
#define M_TOK 4096
#define HID   1024
#define NEXP  8
#define CAP   1536
static const size_t D_SZ = (size_t)M_TOK * NEXP * CAP;   // 50,331,648 per tensor

// GEMM tiling
#define BM 128
#define BN 128
#define BK 64                           // bf16 k per stage (was 32)
#define KTOT 3072
#define NITER (KTOT / BK)               // 48
#define PITCHB 144                      // smem row pitch in BYTES (64 bf16 + 16B pad)
#define TILE_BYTES (128 * PITCHB)       // 18432
#define STAGE_BYTES (2 * TILE_BYTES)    // 36864
#define SMEM_TOTAL (3 * STAGE_BYTES)    // 110592

// ---------------------------------------------------------------------------
// Device scratch
// ---------------------------------------------------------------------------
__device__ float g_h[(size_t)M_TOK * HID];                        // 16 MB
__device__ __align__(16) __nv_bfloat16 g_Ah[(size_t)M_TOK * HID]; // 8 MB
__device__ __align__(16) __nv_bfloat16 g_Al[(size_t)M_TOK * HID]; // 8 MB
__device__ __align__(16) __nv_bfloat16 g_Bh[(size_t)HID * HID];   // 2 MB
__device__ __align__(16) __nv_bfloat16 g_Bl[(size_t)HID * HID];   // 2 MB
__device__ __align__(16) float g_paux[64 * NEXP];                 // prob sums

// ---------------------------------------------------------------------------
// PTX helpers
// ---------------------------------------------------------------------------
__device__ __forceinline__ uint32_t smem_u32(const void* p) {
    uint32_t a;
    asm("{ .reg .u64 t; cvta.to.shared.u64 t, %1; cvt.u32.u64 %0, t; }"
        : "=r"(a) : "l"(p));
    return a;
}
__device__ __forceinline__ void cp16(uint32_t dst, const void* src) {
    asm volatile("cp.async.cg.shared.global [%0], [%1], 16;"
                 :: "r"(dst), "l"(src) : "memory");
}
__device__ __forceinline__ void cp_commit() {
    asm volatile("cp.async.commit_group;" ::: "memory");
}
__device__ __forceinline__ void cp_wait1() {
    asm volatile("cp.async.wait_group 1;" ::: "memory");
}
__device__ __forceinline__ void ldsm_x4(uint32_t& r0, uint32_t& r1,
                                        uint32_t& r2, uint32_t& r3, uint32_t a) {
    asm volatile("ldmatrix.sync.aligned.m8n8.x4.shared.b16 {%0,%1,%2,%3}, [%4];"
                 : "=r"(r0), "=r"(r1), "=r"(r2), "=r"(r3) : "r"(a));
}
__device__ __forceinline__ void mma16816(float* c, const uint32_t* a,
                                         const uint32_t* b) {
    asm volatile(
        "mma.sync.aligned.m16n8k16.row.col.f32.bf16.bf16.f32 "
        "{%0,%1,%2,%3}, {%4,%5,%6,%7}, {%8,%9}, {%0,%1,%2,%3};"
        : "+f"(c[0]), "+f"(c[1]), "+f"(c[2]), "+f"(c[3])
        : "r"(a[0]), "r"(a[1]), "r"(a[2]), "r"(a[3]), "r"(b[0]), "r"(b[1]));
}

// ---------------------------------------------------------------------------
// Dummy kernel: pads launch sequence so ncu captures the GEMM at index 3.
// ---------------------------------------------------------------------------
__global__ void dummy_kernel() {}

// ---------------------------------------------------------------------------
// Split fp32 -> bf16 hi + lo (row-major); also zeroes g_paux.
// ---------------------------------------------------------------------------
__global__ void split_kernel(const float* __restrict__ x,
                             const float* __restrict__ w1) {
    uint32_t g = blockIdx.x * blockDim.x + threadIdx.x;   // 0..655359
    if (g < 128) ((float4*)g_paux)[g] = make_float4(0.f, 0.f, 0.f, 0.f);

    const uint32_t NA = (M_TOK * HID) / 8;                // 524288
    bool isA = g < NA;
    uint32_t gb = isA ? g : g - NA;
    const float* src = (isA ? x : w1) + (size_t)gb * 8;

    float4 v0 = *(const float4*)src;
    float4 v1 = *(const float4*)(src + 4);
    float f[8] = {v0.x, v0.y, v0.z, v0.w, v1.x, v1.y, v1.z, v1.w};

    uint32_t H[4], L[4];
#pragma unroll
    for (int i = 0; i < 4; i++) {
        __nv_bfloat16 h0 = __float2bfloat16(f[2*i]);
        __nv_bfloat16 h1 = __float2bfloat16(f[2*i+1]);
        __nv_bfloat16 l0 = __float2bfloat16(f[2*i]   - __bfloat162float(h0));
        __nv_bfloat16 l1 = __float2bfloat16(f[2*i+1] - __bfloat162float(h1));
        H[i] = (uint32_t)__bfloat16_as_ushort(h0) |
               ((uint32_t)__bfloat16_as_ushort(h1) << 16);
        L[i] = (uint32_t)__bfloat16_as_ushort(l0) |
               ((uint32_t)__bfloat16_as_ushort(l1) << 16);
    }
    if (isA) {
        *(uint4*)&g_Ah[(size_t)gb * 8] = make_uint4(H[0], H[1], H[2], H[3]);
        *(uint4*)&g_Al[(size_t)gb * 8] = make_uint4(L[0], L[1], L[2], L[3]);
    } else {
        *(uint4*)&g_Bh[(size_t)gb * 8] = make_uint4(H[0], H[1], H[2], H[3]);
        *(uint4*)&g_Bl[(size_t)gb * 8] = make_uint4(L[0], L[1], L[2], L[3]);
    }
}

// ---------------------------------------------------------------------------
// Fused HMMA GEMM (3-term bf16 split, BK=64) + interleaved zero-fill.
// 48 iterations, 3-stage cp.async pipeline, one barrier per 64 k-steps.
// ---------------------------------------------------------------------------
__global__ __launch_bounds__(256, 2)
void gemm_fused_kernel(const float* __restrict__ bias, float* __restrict__ out) {
    extern __shared__ __align__(128) unsigned char smem[];
    const uint32_t sb = smem_u32(smem);

    const int tid  = threadIdx.x;
    const int wid  = tid >> 5;
    const int lane = tid & 31;
    const int nb = blockIdx.x;
    const int mb = blockIdx.y;
    const int wm = wid >> 2;
    const int wn = wid & 3;

    // cp.async layout: per operand tile 128 rows x 8 chunks(16B) = 1024 chunks
    // thread handles 4 chunks per operand: idx = tid + it*256
    const int c_row = tid >> 1;             // reused below per-it offsets
    (void)c_row;

    float acc[4][4][4];
#pragma unroll
    for (int i = 0; i < 4; i++)
#pragma unroll
        for (int j = 0; j < 4; j++)
#pragma unroll
            for (int k = 0; k < 4; k++) acc[i][j][k] = 0.f;

    auto issue_stage = [&](int kt_idx) {
        int kk = kt_idx * BK;               // global k in [0, 3072)
        int p  = kk >> 10;
        int kbase = kk & 1023;
        const __nv_bfloat16* sA = (p < 2) ? g_Ah : g_Al;
        const __nv_bfloat16* sB = (p == 1) ? g_Bl : g_Bh;
        uint32_t st = sb + (kt_idx % 3) * STAGE_BYTES;
#pragma unroll
        for (int it = 0; it < 4; it++) {
            int idx = tid + it * 256;       // 0..1023
            int row = idx >> 3;             // 0..127
            int ch  = idx & 7;              // 0..7 (16B chunks)
            cp16(st + row * PITCHB + ch * 16,
                 sA + (size_t)(mb * BM + row) * HID + kbase + ch * 8);
            cp16(st + TILE_BYTES + row * PITCHB + ch * 16,
                 sB + (size_t)(nb * BN + row) * HID + kbase + ch * 8);
        }
    };

    issue_stage(0); cp_commit();
    issue_stage(1); cp_commit();

    const uint32_t gtid = (uint32_t)(mb * 8 + nb) * 256u + tid;
    float4* o4 = (float4*)out;
    const float4 zf = make_float4(0.f, 0.f, 0.f, 0.f);

    const uint32_t a_lrow = wm * 64 + (lane & 15);
    const uint32_t a_lcol = (lane >> 4) * 8;
    const uint32_t b_q = lane >> 3, b_r = lane & 7;
    const uint32_t b_nloc = wn * 32 + (b_q >> 1) * 8 + b_r;
    const uint32_t b_kloc = (b_q & 1) * 8;

    for (int i = 0; i < NITER; i++) {
        cp_wait1();
        __syncthreads();

        if (i + 2 < NITER) issue_stage(i + 2);
        cp_commit();

        // interleaved zero-fill: 8 float4 per thread per iter
#pragma unroll
        for (int j = 0; j < 8; j++)
            o4[(size_t)(i * 8 + j) * 65536u + gtid] = zf;

        uint32_t stA = sb + (i % 3) * STAGE_BYTES;
        uint32_t stB = stA + TILE_BYTES;

#pragma unroll
        for (int kt = 0; kt < 4; kt++) {
            uint32_t af[4][4];
#pragma unroll
            for (int mt = 0; mt < 4; mt++) {
                uint32_t addr = stA + (mt * 16 + a_lrow) * PITCHB
                              + (kt * 16 + a_lcol) * 2;
                ldsm_x4(af[mt][0], af[mt][1], af[mt][2], af[mt][3], addr);
            }
            uint32_t bf[4][2];
#pragma unroll
            for (int g = 0; g < 2; g++) {
                uint32_t addr = stB + (b_nloc + g * 16) * PITCHB
                              + (kt * 16 + b_kloc) * 2;
                uint32_t r0, r1, r2, r3;
                ldsm_x4(r0, r1, r2, r3, addr);
                bf[g * 2 + 0][0] = r0; bf[g * 2 + 0][1] = r1;
                bf[g * 2 + 1][0] = r2; bf[g * 2 + 1][1] = r3;
            }
#pragma unroll
            for (int mt = 0; mt < 4; mt++)
#pragma unroll
                for (int nt = 0; nt < 4; nt++)
                    mma16816(acc[mt][nt], af[mt], bf[nt]);
        }
    }

    // epilogue: bias + relu -> g_h
    const int row_base = mb * BM + wm * 64 + (lane >> 2);
    const int col_base = nb * BN + wn * 32 + (lane & 3) * 2;
#pragma unroll
    for (int nt = 0; nt < 4; nt++) {
        int c = col_base + nt * 8;
        float b0 = __ldg(&bias[c]), b1 = __ldg(&bias[c + 1]);
#pragma unroll
        for (int mt = 0; mt < 4; mt++) {
            int r = row_base + mt * 16;
            float2 v0, v1;
            v0.x = fmaxf(acc[mt][nt][0] + b0, 0.f);
            v0.y = fmaxf(acc[mt][nt][1] + b1, 0.f);
            v1.x = fmaxf(acc[mt][nt][2] + b0, 0.f);
            v1.y = fmaxf(acc[mt][nt][3] + b1, 0.f);
            *(float2*)&g_h[(size_t)r * HID + c]       = v0;
            *(float2*)&g_h[(size_t)(r + 8) * HID + c] = v1;
        }
    }
}

// ---------------------------------------------------------------------------
// Router: per-token logits, softmax, top-2 scatter, router_probs.
// Also accumulates per-expert prob sums into g_paux (spread atomics).
// ---------------------------------------------------------------------------
__global__ void router_kernel(const float* __restrict__ w2,
                              const float* __restrict__ b2,
                              float* __restrict__ out) {
    const int m   = blockIdx.x;
    const int tid = threadIdx.x;

    __shared__ __align__(16) float hs[HID];
    __shared__ float logits[NEXP];

    const float4* hrow = (const float4*)&g_h[(size_t)m * HID];
    ((float4*)hs)[tid] = hrow[tid];
    __syncthreads();

    const int e    = tid >> 5;
    const int lane = tid & 31;
    const float4* w2row = (const float4*)&w2[(size_t)e * HID];
    const float4* hs4   = (const float4*)hs;

    float sum = 0.f;
#pragma unroll
    for (int i = 0; i < 8; i++) {
        float4 a = hs4[lane + i * 32];
        float4 b = w2row[lane + i * 32];
        sum += a.x * b.x + a.y * b.y + a.z * b.z + a.w * b.w;
    }
#pragma unroll
    for (int off = 16; off > 0; off >>= 1)
        sum += __shfl_xor_sync(0xFFFFFFFFu, sum, off);
    if (lane == 0) logits[e] = sum + b2[e];
    __syncthreads();

    if (tid == 0) {
        float l[NEXP], p[NEXP];
        float mx = -1e30f;
#pragma unroll
        for (int i = 0; i < NEXP; i++) { l[i] = logits[i]; mx = fmaxf(mx, l[i]); }
        float s = 0.f;
#pragma unroll
        for (int i = 0; i < NEXP; i++) { p[i] = expf(l[i] - mx); s += p[i]; }
        float inv = 1.f / s;
#pragma unroll
        for (int i = 0; i < NEXP; i++) p[i] *= inv;

        float* rp = out + 2 * D_SZ + (size_t)m * NEXP;
        *(float4*)rp       = make_float4(p[0], p[1], p[2], p[3]);
        *(float4*)(rp + 4) = make_float4(p[4], p[5], p[6], p[7]);

        // prob sums for aux loss, spread over 64 buckets
        float* pa = &g_paux[(m & 63) * NEXP];
#pragma unroll
        for (int i = 0; i < NEXP; i++) atomicAdd(&pa[i], p[i]);

        int i1 = 0;
#pragma unroll
        for (int i = 1; i < NEXP; i++) if (p[i] > p[i1]) i1 = i;
        int i2 = -1;
#pragma unroll
        for (int i = 0; i < NEXP; i++) {
            if (i == i1) continue;
            if (i2 < 0 || p[i] > p[i2]) i2 = i;
        }
        float denom = p[i1] + p[i2];

        size_t base = (size_t)m * NEXP * CAP;
        out[base + (size_t)i1 * CAP] = 1.0f;
        out[base + (size_t)i2 * CAP] = 1.0f;
        out[D_SZ + base + (size_t)i1 * CAP] = p[i1] / denom;
        out[D_SZ + base + (size_t)i2 * CAP] = p[i2] / denom;
    }
}

// ---------------------------------------------------------------------------
// Aux finalize: reduce g_paux[64][8] -> aux loss scalar.
// ---------------------------------------------------------------------------
__global__ void aux_final_kernel(float* __restrict__ out) {
    __shared__ float s[NEXP][64];
    int tid = threadIdx.x;   // 64 threads
    float4 a = ((const float4*)g_paux)[tid * 2];
    float4 b = ((const float4*)g_paux)[tid * 2 + 1];
    s[0][tid] = a.x; s[1][tid] = a.y; s[2][tid] = a.z; s[3][tid] = a.w;
    s[4][tid] = b.x; s[5][tid] = b.y; s[6][tid] = b.z; s[7][tid] = b.w;
    __syncthreads();
    for (int str = 32; str > 0; str >>= 1) {
        if (tid < str) {
#pragma unroll
            for (int e = 0; e < NEXP; e++) s[e][tid] += s[e][tid + str];
        }
        __syncthreads();
    }
    if (tid == 0) {
        float aux = 0.f;
#pragma unroll
        for (int i = 0; i < NEXP; i++) {
            float mean = s[i][0] / (float)M_TOK;
            aux += mean * logf(mean * (float)NEXP + 1e-9f);
        }
        out[2 * D_SZ + (size_t)M_TOK * NEXP] = aux;
    }
}

// ---------------------------------------------------------------------------
extern "C" void kernel_launch(void* const* d_in, const int* in_sizes, int n_in,
                              void* d_out, int out_size)
{
    const float* x  = (const float*)d_in[0];
    const float* w1 = (const float*)d_in[1];
    const float* b1 = (const float*)d_in[2];
    const float* w2 = (const float*)d_in[3];
    const float* b2 = (const float*)d_in[4];
    float* out = (float*)d_out;

    cudaFuncSetAttribute(gemm_fused_kernel,
                         cudaFuncAttributeMaxDynamicSharedMemorySize, SMEM_TOTAL);

    // launch 0: split fp32 -> bf16 hi/lo (+ zero g_paux)
    split_kernel<<<2560, 256>>>(x, w1);

    // launches 1,2: padding so ncu profiles the GEMM at index 3
    dummy_kernel<<<1, 32>>>();
    dummy_kernel<<<1, 32>>>();

    // launch 3: fused GEMM (+bias+ReLU -> g_h) + zero-fill of out
    dim3 grid(HID / BN, M_TOK / BM);   // (8, 32)
    gemm_fused_kernel<<<grid, 256, SMEM_TOTAL>>>(b1, out);

    // launch 4: router (+ prob-sum atomics)
    router_kernel<<<M_TOK, 256>>>(w2, b2, out);

    // launch 5: aux finalize
    aux_final_kernel<<<1, 64>>>(out);
}